// round 2
// baseline (speedup 1.0000x reference)
#include <cuda_runtime.h>
#include <cuda_bf16.h>

// ---------------------------------------------------------------------------
// DownSample: FPS(64->32 strokes) + gathers + conv(1x3,s=2,p=1) 128->256 +
// BatchNorm(batch stats) + tanh-GELU.
//
// Output layout in d_out (float32):
//   [0                  , 524288)    sparse_out      [64,256,32]
//   [524288             , 17301504)  dense_out       [64,256,1024]
//   [17301504           , 17367040)  stk_coor_sampled[64,32,32]
// ---------------------------------------------------------------------------

#define N_STK      64
#define N_HALF     32
#define N_PNT      64
#define N_PNT_H    32
#define COOR_EMB   32
#define BS         64
#define C_IN       128
#define C_OUT      256
#define SP_EMB     256

// scratch (static device allocations are allowed). 16B-aligned: vector-cast.
__device__ __align__(16) int   g_fps_idx[BS * N_HALF];
__device__ __align__(16) float g_wt[C_IN * C_OUT * 4];         // [i][o][k0,k1,k2,pad]
__device__ __align__(16) float g_y[(size_t)BS * C_OUT * 1024]; // conv out [b][o][s][p'] (64 MB)
__device__ __align__(16) float g_scale[C_OUT];
__device__ __align__(16) float g_shift[C_OUT];

// ---------------- f32x2 packed helpers (sm_103a) ----------------
__device__ __forceinline__ unsigned long long pack2(float x, float y) {
    unsigned long long r;
    asm("mov.b64 %0, {%1, %2};" : "=l"(r) : "f"(x), "f"(y));
    return r;
}
__device__ __forceinline__ void unpack2(unsigned long long v, float& x, float& y) {
    asm("mov.b64 {%0, %1}, %2;" : "=f"(x), "=f"(y) : "l"(v));
}
__device__ __forceinline__ unsigned long long fma2(unsigned long long a,
                                                   unsigned long long b,
                                                   unsigned long long c) {
    unsigned long long d;
    asm("fma.rn.f32x2 %0, %1, %2, %3;" : "=l"(d) : "l"(a), "l"(b), "l"(c));
    return d;
}

// ---------------- K1: farthest point sampling -------------------
// One block per batch, 64 threads (one per stroke point).
__global__ void fps_kernel(const float* __restrict__ coor, float* __restrict__ coor_out) {
    int b = blockIdx.x;
    int n = threadIdx.x;

    float p[COOR_EMB];
    const float4* src = (const float4*)(coor + ((size_t)b * N_STK + n) * COOR_EMB);
#pragma unroll
    for (int q = 0; q < COOR_EMB / 4; q++) {
        float4 v = src[q];
        p[4 * q + 0] = v.x; p[4 * q + 1] = v.y; p[4 * q + 2] = v.z; p[4 * q + 3] = v.w;
    }

    __shared__ __align__(16) float cen[COOR_EMB];
    __shared__ float sd[N_STK];
    __shared__ int   si[N_STK];

    float dist = 1e10f;
    int farthest = 0;

    for (int it = 0; it < N_HALF; it++) {
        if (n == 0) g_fps_idx[b * N_HALF + it] = farthest;
        if (n == farthest) {
            float* co = coor_out + ((size_t)b * N_HALF + it) * COOR_EMB;
#pragma unroll
            for (int c = 0; c < COOR_EMB; c++) { cen[c] = p[c]; co[c] = p[c]; }
        }
        __syncthreads();

        float d = 0.f;
#pragma unroll
        for (int c = 0; c < COOR_EMB; c++) {
            float df = p[c] - cen[c];
            d = fmaf(df, df, d);
        }
        dist = fminf(dist, d);

        sd[n] = dist; si[n] = n;
        __syncthreads();
#pragma unroll
        for (int st = 32; st > 0; st >>= 1) {
            if (n < st) {
                float dv = sd[n + st]; int iv = si[n + st];
                // argmax with first-occurrence tie-break (matches jnp.argmax)
                if (dv > sd[n] || (dv == sd[n] && iv < si[n])) { sd[n] = dv; si[n] = iv; }
            }
            __syncthreads();
        }
        farthest = si[0];
        __syncthreads();
    }
}

// ---------------- K2: gather sparse features --------------------
__global__ void gather_sparse(const float* __restrict__ sp, float* __restrict__ out) {
    int gid = blockIdx.x * blockDim.x + threadIdx.x;
    if (gid < BS * SP_EMB * N_HALF) {
        int s = gid & 31;
        int e = (gid >> 5) & 255;
        int b = gid >> 13;
        int sid = g_fps_idx[b * N_HALF + s];
        out[gid] = sp[((size_t)b * SP_EMB + e) * N_STK + sid];
    }
}

// ---------------- K2b: weight transpose -------------------------
// g_wt[(i*256 + o)*4 + k] = w[o*384 + i*3 + k], k<3; pad k=3 with 0.
__global__ void wtrans(const float* __restrict__ w) {
    int idx = blockIdx.x * blockDim.x + threadIdx.x;
    if (idx < C_IN * C_OUT * 4) {
        int k = idx & 3;
        int o = (idx >> 2) & 255;
        int i = idx >> 10;
        g_wt[idx] = (k < 3) ? w[o * (C_IN * 3) + i * 3 + k] : 0.f;
    }
}

// ---------------- K3: gathered strided conv ---------------------
// block = one (stroke s, batch b); 256 threads, one out-channel each.
// y[o,p'] = sum_i  w0*d[i,2p'-1] + w1*d[i,2p'] + w2*d[i,2p'+1]
//   u[j] = d[2j] (even taps), v[j] = d[2j+1] (odd), sw[m] = v[m-1], sw[0]=0.
__global__ __launch_bounds__(256) void conv_kernel(const float* __restrict__ dense,
                                                   const float* __restrict__ bias) {
    __shared__ __align__(16) float sbuf[3 * C_IN * 32];  // 48 KB
    float* su = sbuf;
    float* sv = sbuf + C_IN * 32;
    float* swp = sbuf + 2 * C_IN * 32;

    int s = blockIdx.x;
    int b = blockIdx.y;
    int t = threadIdx.x;

    int sid = g_fps_idx[b * N_HALF + s];
    const float* src = dense + (size_t)b * C_IN * (N_STK * N_PNT) + sid * N_PNT;

    // gather + deinterleave into smem
    for (int e = t; e < C_IN * 32; e += 256) {
        int i = e >> 5, j = e & 31;
        float2 v2 = *(const float2*)(src + (size_t)i * (N_STK * N_PNT) + 2 * j);
        su[i * 32 + j] = v2.x;
        sv[i * 32 + j] = v2.y;
        if (j < 31) swp[i * 32 + j + 1] = v2.y;
        if (j == 0) swp[i * 32] = 0.f;
    }
    __syncthreads();

    int o = t;
    unsigned long long acc[16];
#pragma unroll
    for (int j = 0; j < 16; j++) acc[j] = 0ULL;  // (0.f, 0.f)

    const float4* wt = (const float4*)g_wt;
#pragma unroll 2
    for (int i = 0; i < C_IN; i++) {
        float4 wv = wt[i * C_OUT + o];  // coalesced across threads
        unsigned long long W0 = pack2(wv.x, wv.x);
        unsigned long long W1 = pack2(wv.y, wv.y);
        unsigned long long W2 = pack2(wv.z, wv.z);
        const float* ru = su + i * 32;
        const float* rv = sv + i * 32;
        const float* rw = swp + i * 32;
#pragma unroll
        for (int j = 0; j < 16; j += 2) {
            ulonglong2 U = *(const ulonglong2*)(ru + 2 * j);
            ulonglong2 V = *(const ulonglong2*)(rv + 2 * j);
            ulonglong2 S = *(const ulonglong2*)(rw + 2 * j);
            acc[j]     = fma2(S.x, W0, acc[j]);
            acc[j]     = fma2(U.x, W1, acc[j]);
            acc[j]     = fma2(V.x, W2, acc[j]);
            acc[j + 1] = fma2(S.y, W0, acc[j + 1]);
            acc[j + 1] = fma2(U.y, W1, acc[j + 1]);
            acc[j + 1] = fma2(V.y, W2, acc[j + 1]);
        }
    }
    __syncthreads();

    // stage through smem (stride 33 kills STS bank conflicts), then coalesced STG
    float bval = bias[o];
    float* sy = sbuf;  // 256*33 = 8448 floats < 12288
#pragma unroll
    for (int j = 0; j < 16; j++) {
        float y0, y1;
        unpack2(acc[j], y0, y1);
        sy[o * 33 + 2 * j]     = y0 + bval;
        sy[o * 33 + 2 * j + 1] = y1 + bval;
    }
    __syncthreads();

    float* dst = g_y + (size_t)b * C_OUT * 1024 + s * 32;
    for (int e = t; e < C_OUT * 32; e += 256) {
        int o2 = e >> 5, p = e & 31;
        dst[(size_t)o2 * 1024 + p] = sy[o2 * 33 + p];
    }
}

// ---------------- K4: BN batch stats ----------------------------
__global__ void bn_stats(const float* __restrict__ gamma, const float* __restrict__ beta) {
    int o = blockIdx.x;
    int t = threadIdx.x;
    float s = 0.f, s2 = 0.f;
    for (int b2 = 0; b2 < BS; b2++) {
        const float4* p4 = (const float4*)(g_y + ((size_t)b2 * C_OUT + o) * 1024);
        float4 v = p4[t];  // 256 threads cover 1024 floats exactly
        s  += v.x + v.y + v.z + v.w;
        s2 = fmaf(v.x, v.x, s2); s2 = fmaf(v.y, v.y, s2);
        s2 = fmaf(v.z, v.z, s2); s2 = fmaf(v.w, v.w, s2);
    }
    __shared__ float rs[256], rq[256];
    rs[t] = s; rq[t] = s2;
    __syncthreads();
    for (int st = 128; st > 0; st >>= 1) {
        if (t < st) { rs[t] += rs[t + st]; rq[t] += rq[t + st]; }
        __syncthreads();
    }
    if (t == 0) {
        const float inv_n = 1.f / 65536.f;
        float mean = rs[0] * inv_n;
        float var  = rq[0] * inv_n - mean * mean;
        float r    = rsqrtf(var + 1e-5f);
        float sc   = gamma[o] * r;
        g_scale[o] = sc;
        g_shift[o] = beta[o] - mean * sc;
    }
}

// ---------------- K5: normalize + GELU --------------------------
__device__ __forceinline__ float gelu_f(float x) {
    // jax.nn.gelu approximate=True (tanh form); accurate tanh via expf
    float z = 0.7978845608028654f * fmaf(0.044715f * x, x * x, x);
    float e = __expf(2.f * z);
    float th = 1.f - __fdividef(2.f, e + 1.f);
    return 0.5f * x * (1.f + th);
}

__global__ void bn_gelu(float* __restrict__ out) {
    int i = blockIdx.x * blockDim.x + threadIdx.x;
    if (i < (BS * C_OUT * 1024) / 4) {
        float4 v = ((const float4*)g_y)[i];
        int o = (i >> 8) & 255;  // 256 float4s per (b,o)
        float sc = g_scale[o], sh = g_shift[o];
        v.x = gelu_f(fmaf(v.x, sc, sh));
        v.y = gelu_f(fmaf(v.y, sc, sh));
        v.z = gelu_f(fmaf(v.z, sc, sh));
        v.w = gelu_f(fmaf(v.w, sc, sh));
        ((float4*)out)[i] = v;
    }
}

// ---------------- launch ----------------------------------------
extern "C" void kernel_launch(void* const* d_in, const int* in_sizes, int n_in,
                              void* d_out, int out_size) {
    const float* sparse_fea = (const float*)d_in[0];   // [64,256,64]
    const float* dense_fea  = (const float*)d_in[1];   // [64,128,4096]
    const float* stk_coor   = (const float*)d_in[2];   // [64,64,32]
    const float* conv_w     = (const float*)d_in[3];   // [256,128,1,3]
    const float* conv_b     = (const float*)d_in[4];   // [256]
    const float* bn_gamma   = (const float*)d_in[5];   // [256]
    const float* bn_beta    = (const float*)d_in[6];   // [256]

    float* out = (float*)d_out;
    float* sparse_out = out;                                   // 524288
    float* dense_out  = out + 524288;                          // 16777216
    float* coor_out   = out + 524288 + 16777216;               // 65536

    fps_kernel<<<BS, N_STK>>>(stk_coor, coor_out);
    gather_sparse<<<(BS * SP_EMB * N_HALF + 255) / 256, 256>>>(sparse_fea, sparse_out);
    wtrans<<<(C_IN * C_OUT * 4 + 255) / 256, 256>>>(conv_w);
    conv_kernel<<<dim3(N_HALF, BS), 256>>>(dense_fea, conv_b);
    bn_stats<<<C_OUT, 256>>>(bn_gamma, bn_beta);
    bn_gelu<<<(BS * C_OUT * 1024 / 4 + 255) / 256, 256>>>(dense_out);
}

// round 4
// speedup vs baseline: 1.3002x; 1.3002x over previous
#include <cuda_runtime.h>
#include <cuda_bf16.h>

// ---------------------------------------------------------------------------
// DownSample: FPS(64->32 strokes) + gathers + conv(1x3,s=2,p=1) 128->256 +
// BatchNorm(batch stats) + tanh-GELU.
//
// Output layout in d_out (float32):
//   [0                  , 524288)    sparse_out      [64,256,32]
//   [524288             , 17301504)  dense_out       [64,256,1024]
//   [17301504           , 17367040)  stk_coor_sampled[64,32,32]
// ---------------------------------------------------------------------------

#define N_STK      64
#define N_HALF     32
#define N_PNT      64
#define COOR_EMB   32
#define BS         64
#define C_IN       128
#define C_OUT      256
#define SP_EMB     256

// scratch (static device allocations are allowed). 16B-aligned: vector-cast.
__device__ __align__(16) int   g_fps_idx[BS * N_HALF];
__device__ __align__(16) float g_wt[C_IN * C_OUT * 4];         // [i][o][k0,k1,k2,pad]
__device__ __align__(16) float g_y[(size_t)BS * C_OUT * 1024]; // conv out [b][o][s][p'] (64 MB)
__device__ __align__(16) float g_scale[C_OUT];
__device__ __align__(16) float g_shift[C_OUT];

// ---------------- f32x2 packed helpers (sm_103a) ----------------
__device__ __forceinline__ unsigned long long pack2(float x, float y) {
    unsigned long long r;
    asm("mov.b64 %0, {%1, %2};" : "=l"(r) : "f"(x), "f"(y));
    return r;
}
__device__ __forceinline__ void unpack2(unsigned long long v, float& x, float& y) {
    asm("mov.b64 {%0, %1}, %2;" : "=f"(x), "=f"(y) : "l"(v));
}
__device__ __forceinline__ unsigned long long fma2(unsigned long long a,
                                                   unsigned long long b,
                                                   unsigned long long c) {
    unsigned long long d;
    asm("fma.rn.f32x2 %0, %1, %2, %3;" : "=l"(d) : "l"(a), "l"(b), "l"(c));
    return d;
}

// ---------------- K1: farthest point sampling -------------------
__global__ void fps_kernel(const float* __restrict__ coor, float* __restrict__ coor_out) {
    int b = blockIdx.x;
    int n = threadIdx.x;

    float p[COOR_EMB];
    const float4* src = (const float4*)(coor + ((size_t)b * N_STK + n) * COOR_EMB);
#pragma unroll
    for (int q = 0; q < COOR_EMB / 4; q++) {
        float4 v = src[q];
        p[4 * q + 0] = v.x; p[4 * q + 1] = v.y; p[4 * q + 2] = v.z; p[4 * q + 3] = v.w;
    }

    __shared__ __align__(16) float cen[COOR_EMB];
    __shared__ float sd[N_STK];
    __shared__ int   si[N_STK];

    float dist = 1e10f;
    int farthest = 0;

    for (int it = 0; it < N_HALF; it++) {
        if (n == 0) g_fps_idx[b * N_HALF + it] = farthest;
        if (n == farthest) {
            float* co = coor_out + ((size_t)b * N_HALF + it) * COOR_EMB;
#pragma unroll
            for (int c = 0; c < COOR_EMB; c++) { cen[c] = p[c]; co[c] = p[c]; }
        }
        __syncthreads();

        float d = 0.f;
#pragma unroll
        for (int c = 0; c < COOR_EMB; c++) {
            float df = p[c] - cen[c];
            d = fmaf(df, df, d);
        }
        dist = fminf(dist, d);

        sd[n] = dist; si[n] = n;
        __syncthreads();
#pragma unroll
        for (int st = 32; st > 0; st >>= 1) {
            if (n < st) {
                float dv = sd[n + st]; int iv = si[n + st];
                if (dv > sd[n] || (dv == sd[n] && iv < si[n])) { sd[n] = dv; si[n] = iv; }
            }
            __syncthreads();
        }
        farthest = si[0];
        __syncthreads();
    }
}

// ---------------- K2: gather sparse features --------------------
__global__ void gather_sparse(const float* __restrict__ sp, float* __restrict__ out) {
    int gid = blockIdx.x * blockDim.x + threadIdx.x;
    if (gid < BS * SP_EMB * N_HALF) {
        int s = gid & 31;
        int e = (gid >> 5) & 255;
        int b = gid >> 13;
        int sid = g_fps_idx[b * N_HALF + s];
        out[gid] = sp[((size_t)b * SP_EMB + e) * N_STK + sid];
    }
}

// ---------------- K2b: weight transpose -------------------------
__global__ void wtrans(const float* __restrict__ w) {
    int idx = blockIdx.x * blockDim.x + threadIdx.x;
    if (idx < C_IN * C_OUT * 4) {
        int k = idx & 3;
        int o = (idx >> 2) & 255;
        int i = idx >> 10;
        g_wt[idx] = (k < 3) ? w[o * (C_IN * 3) + i * 3 + k] : 0.f;
    }
}

// ---------------- K3: gathered strided conv ---------------------
// block = one (stroke s, batch b); 128 threads; thread t computes output
// channels o=t and o+128 for all 32 output positions.
// y[o,p'] = w0*d[2p'-1] + w1*d[2p'] + w2*d[2p'+1] summed over i.
// u[j]=d[2j] (even), v[j]=d[2j+1] (odd); shifted operand S built from V regs.
#define ROWP 36   // padded row stride in floats (144B: 16B-aligned, bank-skewed)
__global__ __launch_bounds__(128, 3) void conv_kernel(const float* __restrict__ dense,
                                                      const float* __restrict__ bias) {
    __shared__ __align__(16) float sbuf[2 * C_IN * ROWP];  // 36.9 KB
    float* su = sbuf;
    float* sv = sbuf + C_IN * ROWP;

    int s = blockIdx.x;
    int b = blockIdx.y;
    int t = threadIdx.x;

    int sid = g_fps_idx[b * N_HALF + s];
    const float* src = dense + (size_t)b * C_IN * (N_STK * N_PNT) + sid * N_PNT;

    // fill: thread t loads channel row t (64 floats) and deinterleaves
    {
        const float4* r = (const float4*)(src + (size_t)t * (N_STK * N_PNT));
        float* pu = su + t * ROWP;
        float* pv = sv + t * ROWP;
#pragma unroll
        for (int q = 0; q < 16; q++) {          // 16 float4 = 64 floats
            float4 x = r[q];
            *(float2*)(pu + 2 * q) = make_float2(x.x, x.z);
            *(float2*)(pv + 2 * q) = make_float2(x.y, x.w);
        }
    }
    __syncthreads();

    int o = t;
    unsigned long long a0[16], a1[16];
#pragma unroll
    for (int j = 0; j < 16; j++) { a0[j] = 0ULL; a1[j] = 0ULL; }

    const float4* wt4 = (const float4*)g_wt;
    for (int i = 0; i < C_IN; i++) {
        float4 wA = wt4[i * C_OUT + o];          // channel o taps (coalesced)
        float4 wB = wt4[i * C_OUT + o + 128];    // channel o+128 taps
        unsigned long long WA0 = pack2(wA.x, wA.x);
        unsigned long long WA1 = pack2(wA.y, wA.y);
        unsigned long long WA2 = pack2(wA.z, wA.z);
        unsigned long long WB0 = pack2(wB.x, wB.x);
        unsigned long long WB1 = pack2(wB.y, wB.y);
        unsigned long long WB2 = pack2(wB.z, wB.z);
        const float* ru = su + i * ROWP;
        const float* rv = sv + i * ROWP;
        float prev = 0.f;                        // v[-1] = 0 (left pad)
#pragma unroll
        for (int c = 0; c < 4; c++) {
            ulonglong2 Ua = *(const ulonglong2*)(ru + 8 * c);
            ulonglong2 Ub = *(const ulonglong2*)(ru + 8 * c + 4);
            ulonglong2 Va = *(const ulonglong2*)(rv + 8 * c);
            ulonglong2 Vb = *(const ulonglong2*)(rv + 8 * c + 4);
            unsigned long long Pu[4] = {Ua.x, Ua.y, Ub.x, Ub.y};
            unsigned long long Pv[4] = {Va.x, Va.y, Vb.x, Vb.y};
#pragma unroll
            for (int q = 0; q < 4; q++) {
                int j = 4 * c + q;
                float vlo, vhi; unpack2(Pv[q], vlo, vhi);
                unsigned long long S = pack2(prev, vlo);   // (v[2j-1], v[2j])
                prev = vhi;
                a0[j] = fma2(S,     WA0, a0[j]);
                a0[j] = fma2(Pu[q], WA1, a0[j]);
                a0[j] = fma2(Pv[q], WA2, a0[j]);
                a1[j] = fma2(S,     WB0, a1[j]);
                a1[j] = fma2(Pu[q], WB1, a1[j]);
                a1[j] = fma2(Pv[q], WB2, a1[j]);
            }
        }
    }
    __syncthreads();

    // stage through smem (stride 33: conflict-free), then coalesced STG
    float bv0 = bias[o], bv1 = bias[o + 128];
    float* sy = sbuf;   // needs 256*33 = 8448 floats <= 9216 available
#pragma unroll
    for (int j = 0; j < 16; j++) {
        float y0, y1; unpack2(a0[j], y0, y1);
        sy[o * 33 + 2 * j]     = y0 + bv0;
        sy[o * 33 + 2 * j + 1] = y1 + bv0;
        float z0, z1; unpack2(a1[j], z0, z1);
        sy[(o + 128) * 33 + 2 * j]     = z0 + bv1;
        sy[(o + 128) * 33 + 2 * j + 1] = z1 + bv1;
    }
    __syncthreads();

    float* dst = g_y + (size_t)b * C_OUT * 1024 + s * 32;
    for (int e = t; e < C_OUT * 32; e += 128) {
        int o2 = e >> 5, p = e & 31;
        dst[(size_t)o2 * 1024 + p] = sy[o2 * 33 + p];
    }
}

// ---------------- K4: BN batch stats ----------------------------
__global__ void bn_stats(const float* __restrict__ gamma, const float* __restrict__ beta) {
    int o = blockIdx.x;
    int t = threadIdx.x;
    float s = 0.f, s2 = 0.f;
    for (int b2 = 0; b2 < BS; b2++) {
        const float4* p4 = (const float4*)(g_y + ((size_t)b2 * C_OUT + o) * 1024);
        float4 v = p4[t];
        s  += v.x + v.y + v.z + v.w;
        s2 = fmaf(v.x, v.x, s2); s2 = fmaf(v.y, v.y, s2);
        s2 = fmaf(v.z, v.z, s2); s2 = fmaf(v.w, v.w, s2);
    }
    __shared__ float rs[256], rq[256];
    rs[t] = s; rq[t] = s2;
    __syncthreads();
    for (int st = 128; st > 0; st >>= 1) {
        if (t < st) { rs[t] += rs[t + st]; rq[t] += rq[t + st]; }
        __syncthreads();
    }
    if (t == 0) {
        const float inv_n = 1.f / 65536.f;
        float mean = rs[0] * inv_n;
        float var  = rq[0] * inv_n - mean * mean;
        float r    = rsqrtf(var + 1e-5f);
        float sc   = gamma[o] * r;
        g_scale[o] = sc;
        g_shift[o] = beta[o] - mean * sc;
    }
}

// ---------------- K5: normalize + GELU --------------------------
__device__ __forceinline__ float gelu_f(float x) {
    float z = 0.7978845608028654f * fmaf(0.044715f * x, x * x, x);
    float e = __expf(2.f * z);
    float th = 1.f - __fdividef(2.f, e + 1.f);
    return 0.5f * x * (1.f + th);
}

__global__ void bn_gelu(float* __restrict__ out) {
    int i = blockIdx.x * blockDim.x + threadIdx.x;
    if (i < (BS * C_OUT * 1024) / 4) {
        float4 v = ((const float4*)g_y)[i];
        int o = (i >> 8) & 255;
        float sc = g_scale[o], sh = g_shift[o];
        v.x = gelu_f(fmaf(v.x, sc, sh));
        v.y = gelu_f(fmaf(v.y, sc, sh));
        v.z = gelu_f(fmaf(v.z, sc, sh));
        v.w = gelu_f(fmaf(v.w, sc, sh));
        ((float4*)out)[i] = v;
    }
}

// ---------------- launch ----------------------------------------
extern "C" void kernel_launch(void* const* d_in, const int* in_sizes, int n_in,
                              void* d_out, int out_size) {
    const float* sparse_fea = (const float*)d_in[0];   // [64,256,64]
    const float* dense_fea  = (const float*)d_in[1];   // [64,128,4096]
    const float* stk_coor   = (const float*)d_in[2];   // [64,64,32]
    const float* conv_w     = (const float*)d_in[3];   // [256,128,1,3]
    const float* conv_b     = (const float*)d_in[4];   // [256]
    const float* bn_gamma   = (const float*)d_in[5];   // [256]
    const float* bn_beta    = (const float*)d_in[6];   // [256]

    float* out = (float*)d_out;
    float* sparse_out = out;                                   // 524288
    float* dense_out  = out + 524288;                          // 16777216
    float* coor_out   = out + 524288 + 16777216;               // 65536

    fps_kernel<<<BS, N_STK>>>(stk_coor, coor_out);
    gather_sparse<<<(BS * SP_EMB * N_HALF + 255) / 256, 256>>>(sparse_fea, sparse_out);
    wtrans<<<(C_IN * C_OUT * 4 + 255) / 256, 256>>>(conv_w);
    conv_kernel<<<dim3(N_HALF, BS), 128>>>(dense_fea, conv_b);
    bn_stats<<<C_OUT, 256>>>(bn_gamma, bn_beta);
    bn_gelu<<<(BS * C_OUT * 1024 / 4 + 255) / 256, 256>>>(dense_out);
}